// round 3
// baseline (speedup 1.0000x reference)
#include <cuda_runtime.h>
#include <math.h>

// ---------------------------------------------------------------------------
// EncoderLayer: x[1,4096,512] -> full transformer encoder layer, fp32.
//   Q/K/V = x@Wq.T+b  (NT gemms)
//   flash attention per head (8 heads, d=64)
//   dense proj, add+LN, FFN(relu), add+LN
// ---------------------------------------------------------------------------

#define S_LEN 4096
#define DM    512
#define DFF_  2048
#define NH    8
#define DH    64

// Scratch (device globals: no allocation allowed in kernel_launch)
__device__ float g_Q  [S_LEN * DM];
__device__ float g_K  [S_LEN * DM];
__device__ float g_V  [S_LEN * DM];
__device__ float g_CTX[S_LEN * DM];
__device__ float g_ATT[S_LEN * DM];
__device__ float g_O1 [S_LEN * DM];
__device__ float g_H  [S_LEN * DFF_];
__device__ float g_F  [S_LEN * DM];

// ---------------------------------------------------------------------------
// Generic NT SGEMM: C[M,N] = A[M,K] * B[N,K]^T + bias, optional ReLU.
// 128x128 tile, K-step 8, 256 threads, 8x8 per thread, global prefetch.
// M%128==0, N%128==0, K%8==0 (true for all calls here).
// ---------------------------------------------------------------------------
template<bool RELU>
__global__ void __launch_bounds__(256)
gemm_nt_kernel(const float* __restrict__ A, const float* __restrict__ B,
               const float* __restrict__ bias, float* __restrict__ C,
               int M, int N, int K)
{
    __shared__ float As[8][132];   // [k][m], padded stride 132 (132*4=528=33*16: float4 aligned)
    __shared__ float Bs[8][132];   // [k][n]

    const int t  = threadIdx.x;
    const int tx = t & 15;         // n-tile index (8 cols each)
    const int ty = t >> 4;         // m-tile index (8 rows each)
    const int m0 = blockIdx.y * 128;
    const int n0 = blockIdx.x * 128;

    const int lrow = t >> 1;       // 0..127
    const int lseg = t & 1;        // which half of the 8 k's

    const float* Ag = A + (size_t)(m0 + lrow) * K + lseg * 4;
    const float* Bg = B + (size_t)(n0 + lrow) * K + lseg * 4;

    float acc[8][8];
    #pragma unroll
    for (int i = 0; i < 8; ++i)
        #pragma unroll
        for (int j = 0; j < 8; ++j) acc[i][j] = 0.f;

    float4 a = *(const float4*)(Ag);
    float4 b = *(const float4*)(Bg);

    for (int kt = 0; kt < K; kt += 8) {
        // store current tiles (transposed)
        As[lseg*4+0][lrow] = a.x; As[lseg*4+1][lrow] = a.y;
        As[lseg*4+2][lrow] = a.z; As[lseg*4+3][lrow] = a.w;
        Bs[lseg*4+0][lrow] = b.x; Bs[lseg*4+1][lrow] = b.y;
        Bs[lseg*4+2][lrow] = b.z; Bs[lseg*4+3][lrow] = b.w;
        __syncthreads();

        // prefetch next tiles into registers (hidden behind compute)
        if (kt + 8 < K) {
            a = *(const float4*)(Ag + kt + 8);
            b = *(const float4*)(Bg + kt + 8);
        }

        #pragma unroll
        for (int k = 0; k < 8; ++k) {
            float4 a0 = *(const float4*)&As[k][ty*8];
            float4 a1 = *(const float4*)&As[k][ty*8+4];
            float4 b0 = *(const float4*)&Bs[k][tx*8];
            float4 b1 = *(const float4*)&Bs[k][tx*8+4];
            float ar[8] = {a0.x,a0.y,a0.z,a0.w,a1.x,a1.y,a1.z,a1.w};
            float br[8] = {b0.x,b0.y,b0.z,b0.w,b1.x,b1.y,b1.z,b1.w};
            #pragma unroll
            for (int i = 0; i < 8; ++i)
                #pragma unroll
                for (int j = 0; j < 8; ++j)
                    acc[i][j] = fmaf(ar[i], br[j], acc[i][j]);
        }
        __syncthreads();
    }

    // epilogue: bias (+relu), float4 stores
    float bj[8];
    #pragma unroll
    for (int j = 0; j < 8; ++j) bj[j] = bias[n0 + tx*8 + j];

    #pragma unroll
    for (int i = 0; i < 8; ++i) {
        const int m = m0 + ty*8 + i;
        float out[8];
        #pragma unroll
        for (int j = 0; j < 8; ++j) {
            float v = acc[i][j] + bj[j];
            if (RELU) v = fmaxf(v, 0.f);
            out[j] = v;
        }
        float* cp = C + (size_t)m * N + n0 + tx*8;
        *(float4*)(cp)     = make_float4(out[0], out[1], out[2], out[3]);
        *(float4*)(cp + 4) = make_float4(out[4], out[5], out[6], out[7]);
    }
}

// ---------------------------------------------------------------------------
// Flash attention, fp32. One CTA = (one head, 64-query block). 256 threads.
// BKV = 32 keys per inner tile (128 tiles over S=4096).
// Thread t: q = t>>2 (0..63), dg = t&3. Each thread owns 16 output dims
// (d = dg*16 .. dg*16+15) and computes 8 logits per tile (kk = dg*8 .. +7).
// Row-group of 4 lanes is contiguous in the warp -> shfl reductions.
// Static smem = 44 KB (< 48 KB: no attribute call needed).
// ---------------------------------------------------------------------------
#define QSTR 68
#define KSTR 68
#define PSTR 36

__global__ void __launch_bounds__(256)
flash_attn_kernel(const float* __restrict__ Q, const float* __restrict__ K,
                  const float* __restrict__ V, float* __restrict__ O)
{
    __shared__ float Qs[64 * QSTR];   // 17408 B
    __shared__ float Ks[32 * KSTR];   //  8704 B
    __shared__ float Vs[32 * KSTR];   //  8704 B
    __shared__ float Ps[64 * PSTR];   //  9216 B  (total 44032 B)

    const int t  = threadIdx.x;
    const int h  = blockIdx.y;
    const int q0 = blockIdx.x * 64;
    const int q  = t >> 2;
    const int dg = t & 3;

    // load Q tile [64 x 64] (1024 float4, 4 per thread)
    #pragma unroll
    for (int i = 0; i < 4; ++i) {
        int e  = t + 256 * i;
        int r  = e >> 4;
        int c4 = e & 15;
        float4 v = *(const float4*)(Q + (size_t)(q0 + r) * DM + h * DH + c4 * 4);
        *(float4*)&Qs[r * QSTR + c4 * 4] = v;
    }

    float m = -1e30f, l = 0.f;
    float4 acc0 = make_float4(0,0,0,0), acc1 = acc0, acc2 = acc0, acc3 = acc0;

    const float* qrow = &Qs[q * QSTR];

    for (int kb = 0; kb < S_LEN / 32; ++kb) {
        const int k0 = kb * 32;
        __syncthreads();   // prior PV reads of Vs/Ps done before overwrite
        #pragma unroll
        for (int i = 0; i < 2; ++i) {
            int e  = t + 256 * i;
            int r  = e >> 4;
            int c4 = e & 15;
            *(float4*)&Ks[r * KSTR + c4 * 4] =
                *(const float4*)(K + (size_t)(k0 + r) * DM + h * DH + c4 * 4);
            *(float4*)&Vs[r * KSTR + c4 * 4] =
                *(const float4*)(V + (size_t)(k0 + r) * DM + h * DH + c4 * 4);
        }
        __syncthreads();

        // S = scale * Q K^T : 8 logits per thread
        float s[8];
        float tmax = -1e30f;
        #pragma unroll
        for (int j = 0; j < 8; ++j) {
            const int kk = dg * 8 + j;
            const float4* qp = (const float4*)qrow;
            const float4* kp = (const float4*)&Ks[kk * KSTR];
            float d0 = 0.f, d1 = 0.f, d2 = 0.f, d3 = 0.f;
            #pragma unroll
            for (int d4 = 0; d4 < 16; ++d4) {
                float4 qv = qp[d4];
                float4 kv = kp[d4];
                d0 = fmaf(qv.x, kv.x, d0);
                d1 = fmaf(qv.y, kv.y, d1);
                d2 = fmaf(qv.z, kv.z, d2);
                d3 = fmaf(qv.w, kv.w, d3);
            }
            s[j] = (d0 + d1 + d2 + d3) * 0.125f;   // 1/sqrt(64)
            tmax = fmaxf(tmax, s[j]);
        }
        // row max over the 4-lane group
        tmax = fmaxf(tmax, __shfl_xor_sync(0xffffffffu, tmax, 1));
        tmax = fmaxf(tmax, __shfl_xor_sync(0xffffffffu, tmax, 2));

        const float m_new = fmaxf(m, tmax);
        const float alpha = __expf(m - m_new);

        float p[8];
        float psum = 0.f;
        #pragma unroll
        for (int j = 0; j < 8; ++j) {
            p[j] = __expf(s[j] - m_new);
            psum += p[j];
        }
        psum += __shfl_xor_sync(0xffffffffu, psum, 1);
        psum += __shfl_xor_sync(0xffffffffu, psum, 2);

        l = l * alpha + psum;
        m = m_new;

        acc0.x *= alpha; acc0.y *= alpha; acc0.z *= alpha; acc0.w *= alpha;
        acc1.x *= alpha; acc1.y *= alpha; acc1.z *= alpha; acc1.w *= alpha;
        acc2.x *= alpha; acc2.y *= alpha; acc2.z *= alpha; acc2.w *= alpha;
        acc3.x *= alpha; acc3.y *= alpha; acc3.z *= alpha; acc3.w *= alpha;

        *(float4*)&Ps[q * PSTR + dg * 8]     = make_float4(p[0], p[1], p[2], p[3]);
        *(float4*)&Ps[q * PSTR + dg * 8 + 4] = make_float4(p[4], p[5], p[6], p[7]);
        __syncthreads();

        // acc += P * V (thread owns d = dg*16 .. dg*16+15)
        const float* prow = &Ps[q * PSTR];
        #pragma unroll 8
        for (int kk = 0; kk < 32; ++kk) {
            const float pv = prow[kk];
            const float4* vp = (const float4*)&Vs[kk * KSTR + dg * 16];
            float4 v0 = vp[0], v1 = vp[1], v2 = vp[2], v3 = vp[3];
            acc0.x = fmaf(pv, v0.x, acc0.x); acc0.y = fmaf(pv, v0.y, acc0.y);
            acc0.z = fmaf(pv, v0.z, acc0.z); acc0.w = fmaf(pv, v0.w, acc0.w);
            acc1.x = fmaf(pv, v1.x, acc1.x); acc1.y = fmaf(pv, v1.y, acc1.y);
            acc1.z = fmaf(pv, v1.z, acc1.z); acc1.w = fmaf(pv, v1.w, acc1.w);
            acc2.x = fmaf(pv, v2.x, acc2.x); acc2.y = fmaf(pv, v2.y, acc2.y);
            acc2.z = fmaf(pv, v2.z, acc2.z); acc2.w = fmaf(pv, v2.w, acc2.w);
            acc3.x = fmaf(pv, v3.x, acc3.x); acc3.y = fmaf(pv, v3.y, acc3.y);
            acc3.z = fmaf(pv, v3.z, acc3.z); acc3.w = fmaf(pv, v3.w, acc3.w);
        }
    }

    const float inv = 1.f / l;
    float* op = O + (size_t)(q0 + q) * DM + h * DH + dg * 16;
    *(float4*)(op)      = make_float4(acc0.x*inv, acc0.y*inv, acc0.z*inv, acc0.w*inv);
    *(float4*)(op + 4)  = make_float4(acc1.x*inv, acc1.y*inv, acc1.z*inv, acc1.w*inv);
    *(float4*)(op + 8)  = make_float4(acc2.x*inv, acc2.y*inv, acc2.z*inv, acc2.w*inv);
    *(float4*)(op + 12) = make_float4(acc3.x*inv, acc3.y*inv, acc3.z*inv, acc3.w*inv);
}

// ---------------------------------------------------------------------------
// out[row] = LayerNorm(A[row] + B[row]) * gamma + beta.  One block per row.
// 128 threads, 4 floats each (float4).
// ---------------------------------------------------------------------------
__global__ void __launch_bounds__(128)
add_ln_kernel(const float* __restrict__ A, const float* __restrict__ B,
              const float* __restrict__ gamma, const float* __restrict__ beta,
              float* __restrict__ O)
{
    __shared__ float red[4];
    const int row = blockIdx.x;
    const int t   = threadIdx.x;
    const int wid = t >> 5;
    const int lane = t & 31;

    const size_t base = (size_t)row * DM + t * 4;
    float4 a = *(const float4*)(A + base);
    float4 b = *(const float4*)(B + base);
    float4 v = make_float4(a.x + b.x, a.y + b.y, a.z + b.z, a.w + b.w);

    // sum
    float s = v.x + v.y + v.z + v.w;
    #pragma unroll
    for (int o = 16; o > 0; o >>= 1) s += __shfl_xor_sync(0xffffffffu, s, o);
    if (lane == 0) red[wid] = s;
    __syncthreads();
    const float mu = (red[0] + red[1] + red[2] + red[3]) * (1.f / DM);

    float4 d = make_float4(v.x - mu, v.y - mu, v.z - mu, v.w - mu);
    float ss = d.x*d.x + d.y*d.y + d.z*d.z + d.w*d.w;
    #pragma unroll
    for (int o = 16; o > 0; o >>= 1) ss += __shfl_xor_sync(0xffffffffu, ss, o);
    __syncthreads();               // red reuse
    if (lane == 0) red[wid] = ss;
    __syncthreads();
    const float var  = (red[0] + red[1] + red[2] + red[3]) * (1.f / DM);
    const float rstd = rsqrtf(var + 1e-6f);

    float4 g = *(const float4*)(gamma + t * 4);
    float4 be = *(const float4*)(beta  + t * 4);
    float4 o;
    o.x = d.x * rstd * g.x + be.x;
    o.y = d.y * rstd * g.y + be.y;
    o.z = d.z * rstd * g.z + be.z;
    o.w = d.w * rstd * g.w + be.w;
    *(float4*)(O + base) = o;
}

// ---------------------------------------------------------------------------
// kernel_launch
// ---------------------------------------------------------------------------
extern "C" void kernel_launch(void* const* d_in, const int* in_sizes, int n_in,
                              void* d_out, int out_size)
{
    const float* x       = (const float*)d_in[0];
    const float* wq_w    = (const float*)d_in[1];
    const float* wq_b    = (const float*)d_in[2];
    const float* wk_w    = (const float*)d_in[3];
    const float* wk_b    = (const float*)d_in[4];
    const float* wv_w    = (const float*)d_in[5];
    const float* wv_b    = (const float*)d_in[6];
    const float* dense_w = (const float*)d_in[7];
    const float* dense_b = (const float*)d_in[8];
    const float* l1_w    = (const float*)d_in[9];
    const float* l1_b    = (const float*)d_in[10];
    const float* l2_w    = (const float*)d_in[11];
    const float* l2_b    = (const float*)d_in[12];
    const float* ln1_g   = (const float*)d_in[13];
    const float* ln1_b   = (const float*)d_in[14];
    const float* ln2_g   = (const float*)d_in[15];
    const float* ln2_b   = (const float*)d_in[16];
    float* out = (float*)d_out;

    float *Q, *Kp, *Vp, *CTX, *ATT, *O1, *Hh, *F;
    cudaGetSymbolAddress((void**)&Q,   g_Q);
    cudaGetSymbolAddress((void**)&Kp,  g_K);
    cudaGetSymbolAddress((void**)&Vp,  g_V);
    cudaGetSymbolAddress((void**)&CTX, g_CTX);
    cudaGetSymbolAddress((void**)&ATT, g_ATT);
    cudaGetSymbolAddress((void**)&O1,  g_O1);
    cudaGetSymbolAddress((void**)&Hh,  g_H);
    cudaGetSymbolAddress((void**)&F,   g_F);

    const dim3 gProj(DM / 128, S_LEN / 128);     // (4, 32)
    const dim3 gFF1 (DFF_ / 128, S_LEN / 128);   // (16, 32)

    // QKV projections
    gemm_nt_kernel<false><<<gProj, 256>>>(x, wq_w, wq_b, Q,  S_LEN, DM, DM);
    gemm_nt_kernel<false><<<gProj, 256>>>(x, wk_w, wk_b, Kp, S_LEN, DM, DM);
    gemm_nt_kernel<false><<<gProj, 256>>>(x, wv_w, wv_b, Vp, S_LEN, DM, DM);

    // attention
    flash_attn_kernel<<<dim3(S_LEN / 64, NH), 256>>>(Q, Kp, Vp, CTX);

    // dense proj + add&norm
    gemm_nt_kernel<false><<<gProj, 256>>>(CTX, dense_w, dense_b, ATT, S_LEN, DM, DM);
    add_ln_kernel<<<S_LEN, 128>>>(x, ATT, ln1_g, ln1_b, O1);

    // FFN + add&norm
    gemm_nt_kernel<true ><<<gFF1, 256>>>(O1, l1_w, l1_b, Hh, S_LEN, DFF_, DM);
    gemm_nt_kernel<false><<<gProj, 256>>>(Hh, l2_w, l2_b, F, S_LEN, DM, DFF_);
    add_ln_kernel<<<S_LEN, 128>>>(O1, F, ln2_g, ln2_b, out);
}

// round 4
// speedup vs baseline: 6.9011x; 6.9011x over previous
#include <cuda_runtime.h>
#include <math.h>

// ---------------------------------------------------------------------------
// EncoderLayer: x[1,4096,512] -> full transformer encoder layer.
//   fp32 GEMMs (near fp32-FMA roofline) + tf32 tensor-core flash attention.
// ---------------------------------------------------------------------------

#define S_LEN 4096
#define DM    512
#define DFF_  2048
#define NH    8
#define DH    64

// Scratch (device globals: no allocation allowed in kernel_launch)
__device__ float g_Q  [S_LEN * DM];
__device__ float g_K  [S_LEN * DM];
__device__ float g_V  [S_LEN * DM];
__device__ float g_CTX[S_LEN * DM];
__device__ float g_ATT[S_LEN * DM];
__device__ float g_O1 [S_LEN * DM];
__device__ float g_H  [S_LEN * DFF_];
__device__ float g_F  [S_LEN * DM];

// ---------------------------------------------------------------------------
// Generic NT SGEMM: C[M,N] = A[M,K] * B[N,K]^T + bias, optional ReLU.
// ---------------------------------------------------------------------------
template<bool RELU>
__global__ void __launch_bounds__(256)
gemm_nt_kernel(const float* __restrict__ A, const float* __restrict__ B,
               const float* __restrict__ bias, float* __restrict__ C,
               int M, int N, int K)
{
    __shared__ float As[8][132];
    __shared__ float Bs[8][132];

    const int t  = threadIdx.x;
    const int tx = t & 15;
    const int ty = t >> 4;
    const int m0 = blockIdx.y * 128;
    const int n0 = blockIdx.x * 128;

    const int lrow = t >> 1;
    const int lseg = t & 1;

    const float* Ag = A + (size_t)(m0 + lrow) * K + lseg * 4;
    const float* Bg = B + (size_t)(n0 + lrow) * K + lseg * 4;

    float acc[8][8];
    #pragma unroll
    for (int i = 0; i < 8; ++i)
        #pragma unroll
        for (int j = 0; j < 8; ++j) acc[i][j] = 0.f;

    float4 a = *(const float4*)(Ag);
    float4 b = *(const float4*)(Bg);

    for (int kt = 0; kt < K; kt += 8) {
        As[lseg*4+0][lrow] = a.x; As[lseg*4+1][lrow] = a.y;
        As[lseg*4+2][lrow] = a.z; As[lseg*4+3][lrow] = a.w;
        Bs[lseg*4+0][lrow] = b.x; Bs[lseg*4+1][lrow] = b.y;
        Bs[lseg*4+2][lrow] = b.z; Bs[lseg*4+3][lrow] = b.w;
        __syncthreads();

        if (kt + 8 < K) {
            a = *(const float4*)(Ag + kt + 8);
            b = *(const float4*)(Bg + kt + 8);
        }

        #pragma unroll
        for (int k = 0; k < 8; ++k) {
            float4 a0 = *(const float4*)&As[k][ty*8];
            float4 a1 = *(const float4*)&As[k][ty*8+4];
            float4 b0 = *(const float4*)&Bs[k][tx*8];
            float4 b1 = *(const float4*)&Bs[k][tx*8+4];
            float ar[8] = {a0.x,a0.y,a0.z,a0.w,a1.x,a1.y,a1.z,a1.w};
            float br[8] = {b0.x,b0.y,b0.z,b0.w,b1.x,b1.y,b1.z,b1.w};
            #pragma unroll
            for (int i = 0; i < 8; ++i)
                #pragma unroll
                for (int j = 0; j < 8; ++j)
                    acc[i][j] = fmaf(ar[i], br[j], acc[i][j]);
        }
        __syncthreads();
    }

    float bj[8];
    #pragma unroll
    for (int j = 0; j < 8; ++j) bj[j] = bias[n0 + tx*8 + j];

    #pragma unroll
    for (int i = 0; i < 8; ++i) {
        const int m = m0 + ty*8 + i;
        float out[8];
        #pragma unroll
        for (int j = 0; j < 8; ++j) {
            float v = acc[i][j] + bj[j];
            if (RELU) v = fmaxf(v, 0.f);
            out[j] = v;
        }
        float* cp = C + (size_t)m * N + n0 + tx*8;
        *(float4*)(cp)     = make_float4(out[0], out[1], out[2], out[3]);
        *(float4*)(cp + 4) = make_float4(out[4], out[5], out[6], out[7]);
    }
}

// ---------------------------------------------------------------------------
// tf32 tensor-core flash attention.
// CTA = (head, 64-query block), 128 threads = 4 warps x 16 query rows.
// BKV = 32 keys/tile, K/V double-buffered in smem via cp.async.
// Q held as tf32 A-fragments in registers (pre-scaled by 1/8).
// P re-fragmented through smem (per-warp private rows; __syncwarp only).
// ---------------------------------------------------------------------------
#define BKV  32
#define NT_  (S_LEN / BKV)   // 128
#define KSTR 68              // 68 % 32 == 4  -> conflict-free K B-frag loads
#define VSTR 72              // 72 % 32 == 8  -> conflict-free V B-frag loads
#define PSTR 36              // 36 % 32 == 4  -> conflict-free P A-frag loads

__device__ __forceinline__ unsigned f2tf32(float f) {
    unsigned u;
    asm("cvt.rna.tf32.f32 %0, %1;" : "=r"(u) : "f"(f));
    return u;
}

__device__ __forceinline__ void mma_tf32(float* c, const unsigned* a,
                                         unsigned b0, unsigned b1) {
    asm volatile(
        "mma.sync.aligned.m16n8k8.row.col.f32.tf32.tf32.f32 "
        "{%0,%1,%2,%3}, {%4,%5,%6,%7}, {%8,%9}, {%0,%1,%2,%3};"
        : "+f"(c[0]), "+f"(c[1]), "+f"(c[2]), "+f"(c[3])
        : "r"(a[0]), "r"(a[1]), "r"(a[2]), "r"(a[3]), "r"(b0), "r"(b1));
}

__device__ __forceinline__ void cp16(unsigned dst, const void* src) {
    asm volatile("cp.async.cg.shared.global [%0], [%1], 16;"
                 :: "r"(dst), "l"(src));
}

__global__ void __launch_bounds__(128)
flash_attn_tc_kernel(const float* __restrict__ Q, const float* __restrict__ K,
                     const float* __restrict__ V, float* __restrict__ O)
{
    __shared__ float Ks[2][BKV * KSTR];   // 17408 B
    __shared__ float Vs[2][BKV * VSTR];   // 18432 B
    __shared__ float Ps[64 * PSTR];       //  9216 B   (total 45056 B)

    const int t    = threadIdx.x;
    const int w    = t >> 5;
    const int lane = t & 31;
    const int grp  = lane >> 2;   // 0..7
    const int tig  = lane & 3;    // 0..3
    const int h    = blockIdx.y;
    const int q0   = blockIdx.x * 64;

    // ---- Q fragments: scaled by 1/sqrt(64), converted to tf32, in regs ----
    unsigned qa[8][4];
    {
        const float* Qb = Q + (size_t)(q0 + w * 16) * DM + h * DH;
        #pragma unroll
        for (int kc = 0; kc < 8; ++kc) {
            qa[kc][0] = f2tf32(Qb[(size_t)grp       * DM + kc*8 + tig    ] * 0.125f);
            qa[kc][1] = f2tf32(Qb[(size_t)(grp + 8) * DM + kc*8 + tig    ] * 0.125f);
            qa[kc][2] = f2tf32(Qb[(size_t)grp       * DM + kc*8 + tig + 4] * 0.125f);
            qa[kc][3] = f2tf32(Qb[(size_t)(grp + 8) * DM + kc*8 + tig + 4] * 0.125f);
        }
    }

    float of[8][4];
    #pragma unroll
    for (int n = 0; n < 8; ++n)
        #pragma unroll
        for (int c = 0; c < 4; ++c) of[n][c] = 0.f;

    float m0 = -1e30f, m1 = -1e30f, l0 = 0.f, l1 = 0.f;

    const unsigned ksBase = (unsigned)__cvta_generic_to_shared(&Ks[0][0]);
    const unsigned vsBase = (unsigned)__cvta_generic_to_shared(&Vs[0][0]);

    // tile loader: 32 rows x 64 floats for K and V, 4 x 16B per thread each
    const int lr  = t >> 4;        // 0..7   (+8 per i)
    const int lc4 = t & 15;        // float4 index within row

    #define LOAD_TILE(KB, B)                                                   \
        {                                                                      \
            const size_t krow = (size_t)((KB) * BKV);                          \
            _Pragma("unroll")                                                  \
            for (int i = 0; i < 4; ++i) {                                      \
                const int r = lr + 8 * i;                                      \
                cp16(ksBase + (unsigned)(((B)*BKV*KSTR + r*KSTR + lc4*4) * 4), \
                     K + (krow + r) * DM + h * DH + lc4 * 4);                  \
                cp16(vsBase + (unsigned)(((B)*BKV*VSTR + r*VSTR + lc4*4) * 4), \
                     V + (krow + r) * DM + h * DH + lc4 * 4);                  \
            }                                                                  \
        }

    LOAD_TILE(0, 0);
    asm volatile("cp.async.commit_group;" ::: "memory");

    for (int kb = 0; kb < NT_; ++kb) {
        const int buf = kb & 1;
        if (kb + 1 < NT_) {
            LOAD_TILE(kb + 1, buf ^ 1);
            asm volatile("cp.async.commit_group;" ::: "memory");
            asm volatile("cp.async.wait_group 1;" ::: "memory");
        } else {
            asm volatile("cp.async.wait_group 0;" ::: "memory");
        }
        __syncthreads();

        const float* kbuf = Ks[buf];
        const float* vbuf = Vs[buf];

        // ---- S = scale * Q K^T : 16x32 per warp via m16n8k8 ----
        float sf[4][4];
        #pragma unroll
        for (int n = 0; n < 4; ++n) {
            sf[n][0] = sf[n][1] = sf[n][2] = sf[n][3] = 0.f;
            #pragma unroll
            for (int kc = 0; kc < 8; ++kc) {
                const float* kp = &kbuf[(n*8 + grp) * KSTR + kc*8 + tig];
                unsigned b0 = __float_as_uint(kp[0]);   // tf32 by truncation
                unsigned b1 = __float_as_uint(kp[4]);
                mma_tf32(sf[n], qa[kc], b0, b1);
            }
        }

        // ---- online softmax (rows grp / grp+8; quad = lane%4) ----
        float mx0 = fmaxf(fmaxf(sf[0][0], sf[0][1]), fmaxf(sf[1][0], sf[1][1]));
        mx0 = fmaxf(mx0, fmaxf(fmaxf(sf[2][0], sf[2][1]), fmaxf(sf[3][0], sf[3][1])));
        float mx1 = fmaxf(fmaxf(sf[0][2], sf[0][3]), fmaxf(sf[1][2], sf[1][3]));
        mx1 = fmaxf(mx1, fmaxf(fmaxf(sf[2][2], sf[2][3]), fmaxf(sf[3][2], sf[3][3])));
        mx0 = fmaxf(mx0, __shfl_xor_sync(0xffffffffu, mx0, 1));
        mx0 = fmaxf(mx0, __shfl_xor_sync(0xffffffffu, mx0, 2));
        mx1 = fmaxf(mx1, __shfl_xor_sync(0xffffffffu, mx1, 1));
        mx1 = fmaxf(mx1, __shfl_xor_sync(0xffffffffu, mx1, 2));

        const float mn0 = fmaxf(m0, mx0);
        const float mn1 = fmaxf(m1, mx1);
        const float al0 = __expf(m0 - mn0);
        const float al1 = __expf(m1 - mn1);

        float s0 = 0.f, s1 = 0.f;
        #pragma unroll
        for (int n = 0; n < 4; ++n) {
            sf[n][0] = __expf(sf[n][0] - mn0); s0 += sf[n][0];
            sf[n][1] = __expf(sf[n][1] - mn0); s0 += sf[n][1];
            sf[n][2] = __expf(sf[n][2] - mn1); s1 += sf[n][2];
            sf[n][3] = __expf(sf[n][3] - mn1); s1 += sf[n][3];
        }
        s0 += __shfl_xor_sync(0xffffffffu, s0, 1);
        s0 += __shfl_xor_sync(0xffffffffu, s0, 2);
        s1 += __shfl_xor_sync(0xffffffffu, s1, 1);
        s1 += __shfl_xor_sync(0xffffffffu, s1, 2);

        l0 = l0 * al0 + s0;  m0 = mn0;
        l1 = l1 * al1 + s1;  m1 = mn1;

        #pragma unroll
        for (int n = 0; n < 8; ++n) {
            of[n][0] *= al0; of[n][1] *= al0;
            of[n][2] *= al1; of[n][3] *= al1;
        }

        // ---- store P (tf32 bit patterns) to per-warp-private smem rows ----
        {
            float* pr = &Ps[(w*16 + grp) * PSTR];
            #pragma unroll
            for (int n = 0; n < 4; ++n) {
                pr[n*8 + 2*tig    ]           = __uint_as_float(f2tf32(sf[n][0]));
                pr[n*8 + 2*tig + 1]           = __uint_as_float(f2tf32(sf[n][1]));
                pr[8*PSTR + n*8 + 2*tig    ]  = __uint_as_float(f2tf32(sf[n][2]));
                pr[8*PSTR + n*8 + 2*tig + 1]  = __uint_as_float(f2tf32(sf[n][3]));
            }
        }
        __syncwarp();

        // ---- PV: O(16x64) += P(16x32) V(32x64) ----
        unsigned pa[4][4];
        {
            const float* pr = &Ps[(w*16 + grp) * PSTR];
            #pragma unroll
            for (int kc = 0; kc < 4; ++kc) {
                pa[kc][0] = __float_as_uint(pr[kc*8 + tig]);
                pa[kc][1] = __float_as_uint(pr[8*PSTR + kc*8 + tig]);
                pa[kc][2] = __float_as_uint(pr[kc*8 + tig + 4]);
                pa[kc][3] = __float_as_uint(pr[8*PSTR + kc*8 + tig + 4]);
            }
        }

        #pragma unroll
        for (int n = 0; n < 8; ++n) {
            #pragma unroll
            for (int kc = 0; kc < 4; ++kc) {
                const float* vp = &vbuf[(kc*8 + tig) * VSTR + n*8 + grp];
                unsigned b0 = __float_as_uint(vp[0]);
                unsigned b1 = __float_as_uint(vp[4 * VSTR]);
                mma_tf32(of[n], pa[kc], b0, b1);
            }
        }
        __syncthreads();   // all reads of buf done before next-iter cp.async
    }

    // ---- epilogue: O / l ----
    const float inv0 = 1.f / l0;
    const float inv1 = 1.f / l1;
    float* ob = O + (size_t)(q0 + w*16 + grp) * DM + h * DH;
    #pragma unroll
    for (int n = 0; n < 8; ++n) {
        *(float2*)&ob[n*8 + 2*tig] =
            make_float2(of[n][0] * inv0, of[n][1] * inv0);
        *(float2*)&ob[(size_t)8 * DM + n*8 + 2*tig] =
            make_float2(of[n][2] * inv1, of[n][3] * inv1);
    }
}

// ---------------------------------------------------------------------------
// out[row] = LayerNorm(A[row] + B[row]) * gamma + beta.  One block per row.
// ---------------------------------------------------------------------------
__global__ void __launch_bounds__(128)
add_ln_kernel(const float* __restrict__ A, const float* __restrict__ B,
              const float* __restrict__ gamma, const float* __restrict__ beta,
              float* __restrict__ O)
{
    __shared__ float red[4];
    const int row = blockIdx.x;
    const int t   = threadIdx.x;
    const int wid = t >> 5;
    const int lane = t & 31;

    const size_t base = (size_t)row * DM + t * 4;
    float4 a = *(const float4*)(A + base);
    float4 b = *(const float4*)(B + base);
    float4 v = make_float4(a.x + b.x, a.y + b.y, a.z + b.z, a.w + b.w);

    float s = v.x + v.y + v.z + v.w;
    #pragma unroll
    for (int o = 16; o > 0; o >>= 1) s += __shfl_xor_sync(0xffffffffu, s, o);
    if (lane == 0) red[wid] = s;
    __syncthreads();
    const float mu = (red[0] + red[1] + red[2] + red[3]) * (1.f / DM);

    float4 d = make_float4(v.x - mu, v.y - mu, v.z - mu, v.w - mu);
    float ss = d.x*d.x + d.y*d.y + d.z*d.z + d.w*d.w;
    #pragma unroll
    for (int o = 16; o > 0; o >>= 1) ss += __shfl_xor_sync(0xffffffffu, ss, o);
    __syncthreads();
    if (lane == 0) red[wid] = ss;
    __syncthreads();
    const float var  = (red[0] + red[1] + red[2] + red[3]) * (1.f / DM);
    const float rstd = rsqrtf(var + 1e-6f);

    float4 g  = *(const float4*)(gamma + t * 4);
    float4 be = *(const float4*)(beta  + t * 4);
    float4 o;
    o.x = d.x * rstd * g.x + be.x;
    o.y = d.y * rstd * g.y + be.y;
    o.z = d.z * rstd * g.z + be.z;
    o.w = d.w * rstd * g.w + be.w;
    *(float4*)(O + base) = o;
}

// ---------------------------------------------------------------------------
// kernel_launch
// ---------------------------------------------------------------------------
extern "C" void kernel_launch(void* const* d_in, const int* in_sizes, int n_in,
                              void* d_out, int out_size)
{
    const float* x       = (const float*)d_in[0];
    const float* wq_w    = (const float*)d_in[1];
    const float* wq_b    = (const float*)d_in[2];
    const float* wk_w    = (const float*)d_in[3];
    const float* wk_b    = (const float*)d_in[4];
    const float* wv_w    = (const float*)d_in[5];
    const float* wv_b    = (const float*)d_in[6];
    const float* dense_w = (const float*)d_in[7];
    const float* dense_b = (const float*)d_in[8];
    const float* l1_w    = (const float*)d_in[9];
    const float* l1_b    = (const float*)d_in[10];
    const float* l2_w    = (const float*)d_in[11];
    const float* l2_b    = (const float*)d_in[12];
    const float* ln1_g   = (const float*)d_in[13];
    const float* ln1_b   = (const float*)d_in[14];
    const float* ln2_g   = (const float*)d_in[15];
    const float* ln2_b   = (const float*)d_in[16];
    float* out = (float*)d_out;

    float *Q, *Kp, *Vp, *CTX, *ATT, *O1, *Hh, *F;
    cudaGetSymbolAddress((void**)&Q,   g_Q);
    cudaGetSymbolAddress((void**)&Kp,  g_K);
    cudaGetSymbolAddress((void**)&Vp,  g_V);
    cudaGetSymbolAddress((void**)&CTX, g_CTX);
    cudaGetSymbolAddress((void**)&ATT, g_ATT);
    cudaGetSymbolAddress((void**)&O1,  g_O1);
    cudaGetSymbolAddress((void**)&Hh,  g_H);
    cudaGetSymbolAddress((void**)&F,   g_F);

    const dim3 gProj(DM / 128, S_LEN / 128);     // (4, 32)
    const dim3 gFF1 (DFF_ / 128, S_LEN / 128);   // (16, 32)

    // QKV projections
    gemm_nt_kernel<false><<<gProj, 256>>>(x, wq_w, wq_b, Q,  S_LEN, DM, DM);
    gemm_nt_kernel<false><<<gProj, 256>>>(x, wk_w, wk_b, Kp, S_LEN, DM, DM);
    gemm_nt_kernel<false><<<gProj, 256>>>(x, wv_w, wv_b, Vp, S_LEN, DM, DM);

    // attention (tf32 tensor cores)
    flash_attn_tc_kernel<<<dim3(S_LEN / 64, NH), 128>>>(Q, Kp, Vp, CTX);

    // dense proj + add&norm
    gemm_nt_kernel<false><<<gProj, 256>>>(CTX, dense_w, dense_b, ATT, S_LEN, DM, DM);
    add_ln_kernel<<<S_LEN, 128>>>(x, ATT, ln1_g, ln1_b, O1);

    // FFN + add&norm
    gemm_nt_kernel<true ><<<gFF1, 256>>>(O1, l1_w, l1_b, Hh, S_LEN, DFF_, DM);
    gemm_nt_kernel<false><<<gProj, 256>>>(Hh, l2_w, l2_b, F, S_LEN, DM, DFF_);
    add_ln_kernel<<<S_LEN, 128>>>(O1, F, ln2_g, ln2_b, out);
}

// round 5
// speedup vs baseline: 12.0478x; 1.7458x over previous
#include <cuda_runtime.h>
#include <math.h>

// ---------------------------------------------------------------------------
// EncoderLayer: x[1,4096,512] -> full transformer encoder layer.
//   tf32 tensor-core GEMMs + tf32 tensor-core flash attention.
// ---------------------------------------------------------------------------

#define S_LEN 4096
#define DM    512
#define DFF_  2048
#define NH    8
#define DH    64

// Scratch (device globals: no allocation allowed in kernel_launch)
__device__ float g_Q  [S_LEN * DM];
__device__ float g_K  [S_LEN * DM];
__device__ float g_V  [S_LEN * DM];
__device__ float g_CTX[S_LEN * DM];
__device__ float g_ATT[S_LEN * DM];
__device__ float g_O1 [S_LEN * DM];
__device__ float g_H  [S_LEN * DFF_];
__device__ float g_F  [S_LEN * DM];

// ---------------------------------------------------------------------------
// common PTX helpers
// ---------------------------------------------------------------------------
__device__ __forceinline__ unsigned f2tf32(float f) {
    unsigned u;
    asm("cvt.rna.tf32.f32 %0, %1;" : "=r"(u) : "f"(f));
    return u;
}

__device__ __forceinline__ void mma_tf32(float* c, const unsigned* a,
                                         unsigned b0, unsigned b1) {
    asm volatile(
        "mma.sync.aligned.m16n8k8.row.col.f32.tf32.tf32.f32 "
        "{%0,%1,%2,%3}, {%4,%5,%6,%7}, {%8,%9}, {%0,%1,%2,%3};"
        : "+f"(c[0]), "+f"(c[1]), "+f"(c[2]), "+f"(c[3])
        : "r"(a[0]), "r"(a[1]), "r"(a[2]), "r"(a[3]), "r"(b0), "r"(b1));
}

__device__ __forceinline__ void cp16(unsigned dst, const void* src) {
    asm volatile("cp.async.cg.shared.global [%0], [%1], 16;"
                 :: "r"(dst), "l"(src));
}

// ---------------------------------------------------------------------------
// tf32 tensor-core NT GEMM: C[M,N] = A[M,K] * W[N,K]^T + bias (+ReLU).
// Block tile 128x128, BK=16, double-buffered cp.async, 256 threads.
// 8 warps: warp (wm,wn) owns 64x32 -> 4 m-frags x 4 n-frags, m16n8k8.
// blockIdx.z selects among up to 3 weight/bias/output sets (batched QKV).
// Smem row stride 20 words -> all fragment loads are 32-bank conflict-free.
// ---------------------------------------------------------------------------
#define ASTR 20
#define TILE_WORDS (128 * ASTR)   // 2560 words / tile / matrix

template<bool RELU>
__global__ void __launch_bounds__(256)
gemm_tc_kernel(const float* __restrict__ A,
               const float* __restrict__ W0, const float* __restrict__ bi0, float* __restrict__ C0,
               const float* __restrict__ W1, const float* __restrict__ bi1, float* __restrict__ C1,
               const float* __restrict__ W2, const float* __restrict__ bi2, float* __restrict__ C2,
               int N, int K)
{
    __shared__ float As[2][TILE_WORDS];   // 20480 B
    __shared__ float Bs[2][TILE_WORDS];   // 20480 B

    const float* B    = W0;
    const float* bias = bi0;
    float*       C    = C0;
    if (blockIdx.z == 1) { B = W1; bias = bi1; C = C1; }
    if (blockIdx.z == 2) { B = W2; bias = bi2; C = C2; }

    const int t    = threadIdx.x;
    const int w    = t >> 5;
    const int lane = t & 31;
    const int grp  = lane >> 2;   // 0..7
    const int tig  = lane & 3;    // 0..3
    const int wm   = w >> 2;      // 0..1
    const int wn   = w & 3;       // 0..3
    const int m0   = blockIdx.y * 128;
    const int n0   = blockIdx.x * 128;

    const int lr  = t >> 2;       // 0..63 (+64 second pass)
    const int lc4 = t & 3;        // float4 column within 16-float row chunk

    const unsigned aB = (unsigned)__cvta_generic_to_shared(&As[0][0]);
    const unsigned bB = (unsigned)__cvta_generic_to_shared(&Bs[0][0]);

    float acc[4][4][4];
    #pragma unroll
    for (int i = 0; i < 4; ++i)
        #pragma unroll
        for (int j = 0; j < 4; ++j)
            #pragma unroll
            for (int c = 0; c < 4; ++c) acc[i][j][c] = 0.f;

    #define GLOAD(KT, BUF)                                                        \
        {                                                                         \
            _Pragma("unroll")                                                     \
            for (int p = 0; p < 2; ++p) {                                         \
                const int r = lr + 64 * p;                                        \
                cp16(aB + (unsigned)((((BUF)*TILE_WORDS) + r*ASTR + lc4*4) * 4),  \
                     A + (size_t)(m0 + r) * K + (KT) + lc4 * 4);                  \
                cp16(bB + (unsigned)((((BUF)*TILE_WORDS) + r*ASTR + lc4*4) * 4),  \
                     B + (size_t)(n0 + r) * K + (KT) + lc4 * 4);                  \
            }                                                                     \
        }

    GLOAD(0, 0);
    asm volatile("cp.async.commit_group;" ::: "memory");

    for (int kt = 0; kt < K; kt += 16) {
        const int buf = (kt >> 4) & 1;
        if (kt + 16 < K) {
            GLOAD(kt + 16, buf ^ 1);
            asm volatile("cp.async.commit_group;" ::: "memory");
            asm volatile("cp.async.wait_group 1;" ::: "memory");
        } else {
            asm volatile("cp.async.wait_group 0;" ::: "memory");
        }
        __syncthreads();

        const float* a_s = As[buf];
        const float* b_s = Bs[buf];

        #pragma unroll
        for (int kc = 0; kc < 2; ++kc) {
            unsigned af[4][4];
            #pragma unroll
            for (int i = 0; i < 4; ++i) {
                const float* ap = &a_s[(wm*64 + i*16 + grp) * ASTR + kc*8 + tig];
                af[i][0] = __float_as_uint(ap[0]);           // (grp,   tig)
                af[i][1] = __float_as_uint(ap[8 * ASTR]);    // (grp+8, tig)
                af[i][2] = __float_as_uint(ap[4]);           // (grp,   tig+4)
                af[i][3] = __float_as_uint(ap[8 * ASTR + 4]);// (grp+8, tig+4)
            }
            unsigned bf[4][2];
            #pragma unroll
            for (int j = 0; j < 4; ++j) {
                const float* bp = &b_s[(wn*32 + j*8 + grp) * ASTR + kc*8 + tig];
                bf[j][0] = __float_as_uint(bp[0]);           // (n=grp, k=tig)
                bf[j][1] = __float_as_uint(bp[4]);           // (n=grp, k=tig+4)
            }
            #pragma unroll
            for (int i = 0; i < 4; ++i)
                #pragma unroll
                for (int j = 0; j < 4; ++j)
                    mma_tf32(acc[i][j], af[i], bf[j][0], bf[j][1]);
        }
        __syncthreads();
    }
    #undef GLOAD

    // epilogue: bias (+relu), float2 stores
    #pragma unroll
    for (int j = 0; j < 4; ++j) {
        const int col = n0 + wn*32 + j*8 + 2*tig;
        const float2 bj = *(const float2*)&bias[col];
        #pragma unroll
        for (int i = 0; i < 4; ++i) {
            const int row = m0 + wm*64 + i*16 + grp;
            float2 v0 = make_float2(acc[i][j][0] + bj.x, acc[i][j][1] + bj.y);
            float2 v1 = make_float2(acc[i][j][2] + bj.x, acc[i][j][3] + bj.y);
            if (RELU) {
                v0.x = fmaxf(v0.x, 0.f); v0.y = fmaxf(v0.y, 0.f);
                v1.x = fmaxf(v1.x, 0.f); v1.y = fmaxf(v1.y, 0.f);
            }
            *(float2*)&C[(size_t)row       * N + col] = v0;
            *(float2*)&C[(size_t)(row + 8) * N + col] = v1;
        }
    }
}

// ---------------------------------------------------------------------------
// tf32 tensor-core flash attention (unchanged from R3).
// CTA = (head, 64-query block), 128 threads = 4 warps x 16 query rows.
// ---------------------------------------------------------------------------
#define BKV  32
#define NT_  (S_LEN / BKV)   // 128
#define KSTR 68
#define VSTR 72
#define PSTR 36

__global__ void __launch_bounds__(128)
flash_attn_tc_kernel(const float* __restrict__ Q, const float* __restrict__ K,
                     const float* __restrict__ V, float* __restrict__ O)
{
    __shared__ float Ks[2][BKV * KSTR];
    __shared__ float Vs[2][BKV * VSTR];
    __shared__ float Ps[64 * PSTR];

    const int t    = threadIdx.x;
    const int w    = t >> 5;
    const int lane = t & 31;
    const int grp  = lane >> 2;
    const int tig  = lane & 3;
    const int h    = blockIdx.y;
    const int q0   = blockIdx.x * 64;

    unsigned qa[8][4];
    {
        const float* Qb = Q + (size_t)(q0 + w * 16) * DM + h * DH;
        #pragma unroll
        for (int kc = 0; kc < 8; ++kc) {
            qa[kc][0] = f2tf32(Qb[(size_t)grp       * DM + kc*8 + tig    ] * 0.125f);
            qa[kc][1] = f2tf32(Qb[(size_t)(grp + 8) * DM + kc*8 + tig    ] * 0.125f);
            qa[kc][2] = f2tf32(Qb[(size_t)grp       * DM + kc*8 + tig + 4] * 0.125f);
            qa[kc][3] = f2tf32(Qb[(size_t)(grp + 8) * DM + kc*8 + tig + 4] * 0.125f);
        }
    }

    float of[8][4];
    #pragma unroll
    for (int n = 0; n < 8; ++n)
        #pragma unroll
        for (int c = 0; c < 4; ++c) of[n][c] = 0.f;

    float m0 = -1e30f, m1 = -1e30f, l0 = 0.f, l1 = 0.f;

    const unsigned ksBase = (unsigned)__cvta_generic_to_shared(&Ks[0][0]);
    const unsigned vsBase = (unsigned)__cvta_generic_to_shared(&Vs[0][0]);

    const int lr  = t >> 4;
    const int lc4 = t & 15;

    #define LOAD_TILE(KB, B)                                                   \
        {                                                                      \
            const size_t krow = (size_t)((KB) * BKV);                          \
            _Pragma("unroll")                                                  \
            for (int i = 0; i < 4; ++i) {                                      \
                const int r = lr + 8 * i;                                      \
                cp16(ksBase + (unsigned)(((B)*BKV*KSTR + r*KSTR + lc4*4) * 4), \
                     K + (krow + r) * DM + h * DH + lc4 * 4);                  \
                cp16(vsBase + (unsigned)(((B)*BKV*VSTR + r*VSTR + lc4*4) * 4), \
                     V + (krow + r) * DM + h * DH + lc4 * 4);                  \
            }                                                                  \
        }

    LOAD_TILE(0, 0);
    asm volatile("cp.async.commit_group;" ::: "memory");

    for (int kb = 0; kb < NT_; ++kb) {
        const int buf = kb & 1;
        if (kb + 1 < NT_) {
            LOAD_TILE(kb + 1, buf ^ 1);
            asm volatile("cp.async.commit_group;" ::: "memory");
            asm volatile("cp.async.wait_group 1;" ::: "memory");
        } else {
            asm volatile("cp.async.wait_group 0;" ::: "memory");
        }
        __syncthreads();

        const float* kbuf = Ks[buf];
        const float* vbuf = Vs[buf];

        float sf[4][4];
        #pragma unroll
        for (int n = 0; n < 4; ++n) {
            sf[n][0] = sf[n][1] = sf[n][2] = sf[n][3] = 0.f;
            #pragma unroll
            for (int kc = 0; kc < 8; ++kc) {
                const float* kp = &kbuf[(n*8 + grp) * KSTR + kc*8 + tig];
                unsigned b0 = __float_as_uint(kp[0]);
                unsigned b1 = __float_as_uint(kp[4]);
                mma_tf32(sf[n], qa[kc], b0, b1);
            }
        }

        float mx0 = fmaxf(fmaxf(sf[0][0], sf[0][1]), fmaxf(sf[1][0], sf[1][1]));
        mx0 = fmaxf(mx0, fmaxf(fmaxf(sf[2][0], sf[2][1]), fmaxf(sf[3][0], sf[3][1])));
        float mx1 = fmaxf(fmaxf(sf[0][2], sf[0][3]), fmaxf(sf[1][2], sf[1][3]));
        mx1 = fmaxf(mx1, fmaxf(fmaxf(sf[2][2], sf[2][3]), fmaxf(sf[3][2], sf[3][3])));
        mx0 = fmaxf(mx0, __shfl_xor_sync(0xffffffffu, mx0, 1));
        mx0 = fmaxf(mx0, __shfl_xor_sync(0xffffffffu, mx0, 2));
        mx1 = fmaxf(mx1, __shfl_xor_sync(0xffffffffu, mx1, 1));
        mx1 = fmaxf(mx1, __shfl_xor_sync(0xffffffffu, mx1, 2));

        const float mn0 = fmaxf(m0, mx0);
        const float mn1 = fmaxf(m1, mx1);
        const float al0 = __expf(m0 - mn0);
        const float al1 = __expf(m1 - mn1);

        float s0 = 0.f, s1 = 0.f;
        #pragma unroll
        for (int n = 0; n < 4; ++n) {
            sf[n][0] = __expf(sf[n][0] - mn0); s0 += sf[n][0];
            sf[n][1] = __expf(sf[n][1] - mn0); s0 += sf[n][1];
            sf[n][2] = __expf(sf[n][2] - mn1); s1 += sf[n][2];
            sf[n][3] = __expf(sf[n][3] - mn1); s1 += sf[n][3];
        }
        s0 += __shfl_xor_sync(0xffffffffu, s0, 1);
        s0 += __shfl_xor_sync(0xffffffffu, s0, 2);
        s1 += __shfl_xor_sync(0xffffffffu, s1, 1);
        s1 += __shfl_xor_sync(0xffffffffu, s1, 2);

        l0 = l0 * al0 + s0;  m0 = mn0;
        l1 = l1 * al1 + s1;  m1 = mn1;

        #pragma unroll
        for (int n = 0; n < 8; ++n) {
            of[n][0] *= al0; of[n][1] *= al0;
            of[n][2] *= al1; of[n][3] *= al1;
        }

        {
            float* pr = &Ps[(w*16 + grp) * PSTR];
            #pragma unroll
            for (int n = 0; n < 4; ++n) {
                pr[n*8 + 2*tig    ]          = __uint_as_float(f2tf32(sf[n][0]));
                pr[n*8 + 2*tig + 1]          = __uint_as_float(f2tf32(sf[n][1]));
                pr[8*PSTR + n*8 + 2*tig    ] = __uint_as_float(f2tf32(sf[n][2]));
                pr[8*PSTR + n*8 + 2*tig + 1] = __uint_as_float(f2tf32(sf[n][3]));
            }
        }
        __syncwarp();

        unsigned pa[4][4];
        {
            const float* pr = &Ps[(w*16 + grp) * PSTR];
            #pragma unroll
            for (int kc = 0; kc < 4; ++kc) {
                pa[kc][0] = __float_as_uint(pr[kc*8 + tig]);
                pa[kc][1] = __float_as_uint(pr[8*PSTR + kc*8 + tig]);
                pa[kc][2] = __float_as_uint(pr[kc*8 + tig + 4]);
                pa[kc][3] = __float_as_uint(pr[8*PSTR + kc*8 + tig + 4]);
            }
        }

        #pragma unroll
        for (int n = 0; n < 8; ++n) {
            #pragma unroll
            for (int kc = 0; kc < 4; ++kc) {
                const float* vp = &vbuf[(kc*8 + tig) * VSTR + n*8 + grp];
                unsigned b0 = __float_as_uint(vp[0]);
                unsigned b1 = __float_as_uint(vp[4 * VSTR]);
                mma_tf32(of[n], pa[kc], b0, b1);
            }
        }
        __syncthreads();
    }

    const float inv0 = 1.f / l0;
    const float inv1 = 1.f / l1;
    float* ob = O + (size_t)(q0 + w*16 + grp) * DM + h * DH;
    #pragma unroll
    for (int n = 0; n < 8; ++n) {
        *(float2*)&ob[n*8 + 2*tig] =
            make_float2(of[n][0] * inv0, of[n][1] * inv0);
        *(float2*)&ob[(size_t)8 * DM + n*8 + 2*tig] =
            make_float2(of[n][2] * inv1, of[n][3] * inv1);
    }
}

// ---------------------------------------------------------------------------
// out[row] = LayerNorm(A[row] + B[row]) * gamma + beta.  One block per row.
// ---------------------------------------------------------------------------
__global__ void __launch_bounds__(128)
add_ln_kernel(const float* __restrict__ A, const float* __restrict__ B,
              const float* __restrict__ gamma, const float* __restrict__ beta,
              float* __restrict__ O)
{
    __shared__ float red[4];
    const int row = blockIdx.x;
    const int t   = threadIdx.x;
    const int wid = t >> 5;
    const int lane = t & 31;

    const size_t base = (size_t)row * DM + t * 4;
    float4 a = *(const float4*)(A + base);
    float4 b = *(const float4*)(B + base);
    float4 v = make_float4(a.x + b.x, a.y + b.y, a.z + b.z, a.w + b.w);

    float s = v.x + v.y + v.z + v.w;
    #pragma unroll
    for (int o = 16; o > 0; o >>= 1) s += __shfl_xor_sync(0xffffffffu, s, o);
    if (lane == 0) red[wid] = s;
    __syncthreads();
    const float mu = (red[0] + red[1] + red[2] + red[3]) * (1.f / DM);

    float4 d = make_float4(v.x - mu, v.y - mu, v.z - mu, v.w - mu);
    float ss = d.x*d.x + d.y*d.y + d.z*d.z + d.w*d.w;
    #pragma unroll
    for (int o = 16; o > 0; o >>= 1) ss += __shfl_xor_sync(0xffffffffu, ss, o);
    __syncthreads();
    if (lane == 0) red[wid] = ss;
    __syncthreads();
    const float var  = (red[0] + red[1] + red[2] + red[3]) * (1.f / DM);
    const float rstd = rsqrtf(var + 1e-6f);

    float4 g  = *(const float4*)(gamma + t * 4);
    float4 be = *(const float4*)(beta  + t * 4);
    float4 o;
    o.x = d.x * rstd * g.x + be.x;
    o.y = d.y * rstd * g.y + be.y;
    o.z = d.z * rstd * g.z + be.z;
    o.w = d.w * rstd * g.w + be.w;
    *(float4*)(O + base) = o;
}

// ---------------------------------------------------------------------------
// kernel_launch
// ---------------------------------------------------------------------------
extern "C" void kernel_launch(void* const* d_in, const int* in_sizes, int n_in,
                              void* d_out, int out_size)
{
    const float* x       = (const float*)d_in[0];
    const float* wq_w    = (const float*)d_in[1];
    const float* wq_b    = (const float*)d_in[2];
    const float* wk_w    = (const float*)d_in[3];
    const float* wk_b    = (const float*)d_in[4];
    const float* wv_w    = (const float*)d_in[5];
    const float* wv_b    = (const float*)d_in[6];
    const float* dense_w = (const float*)d_in[7];
    const float* dense_b = (const float*)d_in[8];
    const float* l1_w    = (const float*)d_in[9];
    const float* l1_b    = (const float*)d_in[10];
    const float* l2_w    = (const float*)d_in[11];
    const float* l2_b    = (const float*)d_in[12];
    const float* ln1_g   = (const float*)d_in[13];
    const float* ln1_b   = (const float*)d_in[14];
    const float* ln2_g   = (const float*)d_in[15];
    const float* ln2_b   = (const float*)d_in[16];
    float* out = (float*)d_out;

    float *Q, *Kp, *Vp, *CTX, *ATT, *O1, *Hh, *F;
    cudaGetSymbolAddress((void**)&Q,   g_Q);
    cudaGetSymbolAddress((void**)&Kp,  g_K);
    cudaGetSymbolAddress((void**)&Vp,  g_V);
    cudaGetSymbolAddress((void**)&CTX, g_CTX);
    cudaGetSymbolAddress((void**)&ATT, g_ATT);
    cudaGetSymbolAddress((void**)&O1,  g_O1);
    cudaGetSymbolAddress((void**)&Hh,  g_H);
    cudaGetSymbolAddress((void**)&F,   g_F);

    // QKV projections, batched into one launch (384 CTAs)
    gemm_tc_kernel<false><<<dim3(DM/128, S_LEN/128, 3), 256>>>(
        x,
        wq_w, wq_b, Q,
        wk_w, wk_b, Kp,
        wv_w, wv_b, Vp,
        DM, DM);

    // attention (tf32 tensor cores)
    flash_attn_tc_kernel<<<dim3(S_LEN / 64, NH), 128>>>(Q, Kp, Vp, CTX);

    // dense proj + add&norm
    gemm_tc_kernel<false><<<dim3(DM/128, S_LEN/128, 1), 256>>>(
        CTX,
        dense_w, dense_b, ATT,
        dense_w, dense_b, ATT,
        dense_w, dense_b, ATT,
        DM, DM);
    add_ln_kernel<<<S_LEN, 128>>>(x, ATT, ln1_g, ln1_b, O1);

    // FFN + add&norm
    gemm_tc_kernel<true><<<dim3(DFF_/128, S_LEN/128, 1), 256>>>(
        O1,
        l1_w, l1_b, Hh,
        l1_w, l1_b, Hh,
        l1_w, l1_b, Hh,
        DFF_, DM);
    gemm_tc_kernel<false><<<dim3(DM/128, S_LEN/128, 1), 256>>>(
        Hh,
        l2_w, l2_b, F,
        l2_w, l2_b, F,
        l2_w, l2_b, F,
        DM, DFF_);
    add_ln_kernel<<<S_LEN, 128>>>(O1, F, ln2_g, ln2_b, out);
}

// round 6
// speedup vs baseline: 16.4371x; 1.3643x over previous
#include <cuda_runtime.h>
#include <cuda_bf16.h>
#include <math.h>

// ---------------------------------------------------------------------------
// EncoderLayer: x[1,4096,512] -> full transformer encoder layer.
//   tf32 tensor-core GEMMs + bf16 (m16n8k16) flash attention.
// ---------------------------------------------------------------------------

#define S_LEN 4096
#define DM    512
#define DFF_  2048
#define NH    8
#define DH    64

// Scratch (device globals: no allocation allowed in kernel_launch)
__device__ __nv_bfloat16 g_Qb[S_LEN * DM];
__device__ __nv_bfloat16 g_Kb[S_LEN * DM];
__device__ __nv_bfloat16 g_Vb[S_LEN * DM];
__device__ float g_CTX[S_LEN * DM];
__device__ float g_ATT[S_LEN * DM];
__device__ float g_O1 [S_LEN * DM];
__device__ float g_H  [S_LEN * DFF_];
__device__ float g_F  [S_LEN * DM];

// ---------------------------------------------------------------------------
// PTX helpers
// ---------------------------------------------------------------------------
__device__ __forceinline__ void mma_tf32(float* c, const unsigned* a,
                                         unsigned b0, unsigned b1) {
    asm volatile(
        "mma.sync.aligned.m16n8k8.row.col.f32.tf32.tf32.f32 "
        "{%0,%1,%2,%3}, {%4,%5,%6,%7}, {%8,%9}, {%0,%1,%2,%3};"
        : "+f"(c[0]), "+f"(c[1]), "+f"(c[2]), "+f"(c[3])
        : "r"(a[0]), "r"(a[1]), "r"(a[2]), "r"(a[3]), "r"(b0), "r"(b1));
}

__device__ __forceinline__ void mma_bf16(float* c, const unsigned* a,
                                         unsigned b0, unsigned b1) {
    asm volatile(
        "mma.sync.aligned.m16n8k16.row.col.f32.bf16.bf16.f32 "
        "{%0,%1,%2,%3}, {%4,%5,%6,%7}, {%8,%9}, {%0,%1,%2,%3};"
        : "+f"(c[0]), "+f"(c[1]), "+f"(c[2]), "+f"(c[3])
        : "r"(a[0]), "r"(a[1]), "r"(a[2]), "r"(a[3]), "r"(b0), "r"(b1));
}

__device__ __forceinline__ void ldsm_x4(unsigned& d0, unsigned& d1,
                                        unsigned& d2, unsigned& d3, unsigned addr) {
    asm volatile("ldmatrix.sync.aligned.m8n8.x4.shared.b16 {%0,%1,%2,%3}, [%4];"
                 : "=r"(d0), "=r"(d1), "=r"(d2), "=r"(d3) : "r"(addr));
}

__device__ __forceinline__ void ldsm_x4_t(unsigned& d0, unsigned& d1,
                                          unsigned& d2, unsigned& d3, unsigned addr) {
    asm volatile("ldmatrix.sync.aligned.m8n8.x4.trans.shared.b16 {%0,%1,%2,%3}, [%4];"
                 : "=r"(d0), "=r"(d1), "=r"(d2), "=r"(d3) : "r"(addr));
}

__device__ __forceinline__ unsigned pack_bf16(float lo, float hi) {
    unsigned r;
    asm("cvt.rn.bf16x2.f32 %0, %1, %2;" : "=r"(r) : "f"(hi), "f"(lo));
    return r;
}

__device__ __forceinline__ void cp16(unsigned dst, const void* src) {
    asm volatile("cp.async.cg.shared.global [%0], [%1], 16;"
                 :: "r"(dst), "l"(src));
}

// ---------------------------------------------------------------------------
// tf32 tensor-core NT GEMM: C[M,N] = (A[M,K] * W[N,K]^T + bias) * scale (+ReLU).
// Block tile 128x128, BK=16, double-buffered cp.async, 256 threads.
// blockIdx.z selects among up to 3 weight/bias/output sets (batched QKV).
// BF16OUT: write __nv_bfloat16 output (for attention Q/K/V).
// ---------------------------------------------------------------------------
#define ASTR 20
#define TILE_WORDS (128 * ASTR)

template<bool RELU, bool BF16OUT>
__global__ void __launch_bounds__(256)
gemm_tc_kernel(const float* __restrict__ A,
               const float* __restrict__ W0, const float* __restrict__ bi0, void* __restrict__ C0,
               const float* __restrict__ W1, const float* __restrict__ bi1, void* __restrict__ C1,
               const float* __restrict__ W2, const float* __restrict__ bi2, void* __restrict__ C2,
               int N, int K, float s0, float s1, float s2)
{
    __shared__ float As[2][TILE_WORDS];
    __shared__ float Bs[2][TILE_WORDS];

    const float* B    = W0;
    const float* bias = bi0;
    void*        Cv   = C0;
    float        scl  = s0;
    if (blockIdx.z == 1) { B = W1; bias = bi1; Cv = C1; scl = s1; }
    if (blockIdx.z == 2) { B = W2; bias = bi2; Cv = C2; scl = s2; }

    const int t    = threadIdx.x;
    const int w    = t >> 5;
    const int lane = t & 31;
    const int grp  = lane >> 2;
    const int tig  = lane & 3;
    const int wm   = w >> 2;
    const int wn   = w & 3;
    const int m0   = blockIdx.y * 128;
    const int n0   = blockIdx.x * 128;

    const int lr  = t >> 2;
    const int lc4 = t & 3;

    const unsigned aB = (unsigned)__cvta_generic_to_shared(&As[0][0]);
    const unsigned bB = (unsigned)__cvta_generic_to_shared(&Bs[0][0]);

    float acc[4][4][4];
    #pragma unroll
    for (int i = 0; i < 4; ++i)
        #pragma unroll
        for (int j = 0; j < 4; ++j)
            #pragma unroll
            for (int c = 0; c < 4; ++c) acc[i][j][c] = 0.f;

    #define GLOAD(KT, BUF)                                                        \
        {                                                                         \
            _Pragma("unroll")                                                     \
            for (int p = 0; p < 2; ++p) {                                         \
                const int r = lr + 64 * p;                                        \
                cp16(aB + (unsigned)((((BUF)*TILE_WORDS) + r*ASTR + lc4*4) * 4),  \
                     A + (size_t)(m0 + r) * K + (KT) + lc4 * 4);                  \
                cp16(bB + (unsigned)((((BUF)*TILE_WORDS) + r*ASTR + lc4*4) * 4),  \
                     B + (size_t)(n0 + r) * K + (KT) + lc4 * 4);                  \
            }                                                                     \
        }

    GLOAD(0, 0);
    asm volatile("cp.async.commit_group;" ::: "memory");

    for (int kt = 0; kt < K; kt += 16) {
        const int buf = (kt >> 4) & 1;
        if (kt + 16 < K) {
            GLOAD(kt + 16, buf ^ 1);
            asm volatile("cp.async.commit_group;" ::: "memory");
            asm volatile("cp.async.wait_group 1;" ::: "memory");
        } else {
            asm volatile("cp.async.wait_group 0;" ::: "memory");
        }
        __syncthreads();

        const float* a_s = As[buf];
        const float* b_s = Bs[buf];

        #pragma unroll
        for (int kc = 0; kc < 2; ++kc) {
            unsigned af[4][4];
            #pragma unroll
            for (int i = 0; i < 4; ++i) {
                const float* ap = &a_s[(wm*64 + i*16 + grp) * ASTR + kc*8 + tig];
                af[i][0] = __float_as_uint(ap[0]);
                af[i][1] = __float_as_uint(ap[8 * ASTR]);
                af[i][2] = __float_as_uint(ap[4]);
                af[i][3] = __float_as_uint(ap[8 * ASTR + 4]);
            }
            unsigned bf[4][2];
            #pragma unroll
            for (int j = 0; j < 4; ++j) {
                const float* bp = &b_s[(wn*32 + j*8 + grp) * ASTR + kc*8 + tig];
                bf[j][0] = __float_as_uint(bp[0]);
                bf[j][1] = __float_as_uint(bp[4]);
            }
            #pragma unroll
            for (int i = 0; i < 4; ++i)
                #pragma unroll
                for (int j = 0; j < 4; ++j)
                    mma_tf32(acc[i][j], af[i], bf[j][0], bf[j][1]);
        }
        __syncthreads();
    }
    #undef GLOAD

    // epilogue: (acc + bias) * scale (+relu)
    #pragma unroll
    for (int j = 0; j < 4; ++j) {
        const int col = n0 + wn*32 + j*8 + 2*tig;
        const float2 bj = *(const float2*)&bias[col];
        #pragma unroll
        for (int i = 0; i < 4; ++i) {
            const int row = m0 + wm*64 + i*16 + grp;
            float2 v0 = make_float2((acc[i][j][0] + bj.x) * scl, (acc[i][j][1] + bj.y) * scl);
            float2 v1 = make_float2((acc[i][j][2] + bj.x) * scl, (acc[i][j][3] + bj.y) * scl);
            if (RELU) {
                v0.x = fmaxf(v0.x, 0.f); v0.y = fmaxf(v0.y, 0.f);
                v1.x = fmaxf(v1.x, 0.f); v1.y = fmaxf(v1.y, 0.f);
            }
            if (BF16OUT) {
                __nv_bfloat16* Cb = (__nv_bfloat16*)Cv;
                *(__nv_bfloat162*)&Cb[(size_t)row       * N + col] = __float22bfloat162_rn(v0);
                *(__nv_bfloat162*)&Cb[(size_t)(row + 8) * N + col] = __float22bfloat162_rn(v1);
            } else {
                float* Cf = (float*)Cv;
                *(float2*)&Cf[(size_t)row       * N + col] = v0;
                *(float2*)&Cf[(size_t)(row + 8) * N + col] = v1;
            }
        }
    }
}

// ---------------------------------------------------------------------------
// bf16 tensor-core flash attention (m16n8k16 + ldmatrix).
// CTA = (head, 64-query block), 128 threads = 4 warps x 16 query rows.
// BKV = 32 keys/tile, K/V (bf16) double-buffered via cp.async.
// Q (pre-scaled by 1/8, bf16) held as A-fragments in registers.
// P re-fragmented through per-warp-private bf16 smem rows (__syncwarp only).
// V B-fragments via ldmatrix.x4.trans; K B-fragments via ldmatrix.x4.
// ---------------------------------------------------------------------------
#define BKV   32
#define NT_   (S_LEN / BKV)   // 128
#define KSTRb 72              // bf16 units; 144B row stride (9 x 16B)
#define PSTRb 40              // bf16 units; 80B row stride

__global__ void __launch_bounds__(128)
flash_attn_bf16_kernel(const __nv_bfloat16* __restrict__ Q,
                       const __nv_bfloat16* __restrict__ K,
                       const __nv_bfloat16* __restrict__ V,
                       float* __restrict__ O)
{
    __shared__ __nv_bfloat16 Ks[2][BKV * KSTRb];   // 9216 B
    __shared__ __nv_bfloat16 Vs[2][BKV * KSTRb];   // 9216 B
    __shared__ __nv_bfloat16 Ps[64 * PSTRb];       // 5120 B

    const int t    = threadIdx.x;
    const int w    = t >> 5;
    const int lane = t & 31;
    const int grp  = lane >> 2;   // 0..7
    const int tig  = lane & 3;    // 0..3
    const int h    = blockIdx.y;
    const int q0   = blockIdx.x * 64;

    // ---- Q fragments (already scaled by 1/8 at QKV epilogue) ----
    unsigned qa[4][4];
    {
        const __nv_bfloat16* Qb = Q + (size_t)(q0 + w * 16) * DM + h * DH;
        #pragma unroll
        for (int kc = 0; kc < 4; ++kc) {
            qa[kc][0] = *(const unsigned*)&Qb[(size_t)grp       * DM + kc*16 + 2*tig];
            qa[kc][1] = *(const unsigned*)&Qb[(size_t)(grp + 8) * DM + kc*16 + 2*tig];
            qa[kc][2] = *(const unsigned*)&Qb[(size_t)grp       * DM + kc*16 + 8 + 2*tig];
            qa[kc][3] = *(const unsigned*)&Qb[(size_t)(grp + 8) * DM + kc*16 + 8 + 2*tig];
        }
    }

    float of[8][4];
    #pragma unroll
    for (int n = 0; n < 8; ++n)
        #pragma unroll
        for (int c = 0; c < 4; ++c) of[n][c] = 0.f;

    float m0 = -1e30f, m1 = -1e30f, l0 = 0.f, l1 = 0.f;

    const unsigned ksBase = (unsigned)__cvta_generic_to_shared(&Ks[0][0]);
    const unsigned vsBase = (unsigned)__cvta_generic_to_shared(&Vs[0][0]);

    // tile loader: 32 rows x 128B per matrix; 128 threads x 2 chunks each
    const int lr = t >> 3;        // 0..15 (+16 second pass)
    const int c8 = t & 7;         // 16B chunk within 128B row

    #define LOAD_TILE(KB, B)                                                          \
        {                                                                             \
            const size_t krow = (size_t)((KB) * BKV);                                 \
            _Pragma("unroll")                                                         \
            for (int i = 0; i < 2; ++i) {                                             \
                const int r = lr + 16 * i;                                            \
                cp16(ksBase + (unsigned)((((B)*BKV + r)*KSTRb + c8*8) * 2),           \
                     K + (krow + r) * DM + h * DH + c8 * 8);                          \
                cp16(vsBase + (unsigned)((((B)*BKV + r)*KSTRb + c8*8) * 2),           \
                     V + (krow + r) * DM + h * DH + c8 * 8);                          \
            }                                                                         \
        }

    LOAD_TILE(0, 0);
    asm volatile("cp.async.commit_group;" ::: "memory");

    for (int kb = 0; kb < NT_; ++kb) {
        const int buf = kb & 1;
        if (kb + 1 < NT_) {
            LOAD_TILE(kb + 1, buf ^ 1);
            asm volatile("cp.async.commit_group;" ::: "memory");
            asm volatile("cp.async.wait_group 1;" ::: "memory");
        } else {
            asm volatile("cp.async.wait_group 0;" ::: "memory");
        }
        __syncthreads();

        const unsigned kbuf = ksBase + (unsigned)(buf * BKV * KSTRb * 2);
        const unsigned vbuf = vsBase + (unsigned)(buf * BKV * KSTRb * 2);

        // ---- S = Qs K^T : 16x32 per warp via m16n8k16 + ldmatrix.x4 ----
        float sf[4][4];
        #pragma unroll
        for (int n = 0; n < 4; ++n) {
            sf[n][0] = sf[n][1] = sf[n][2] = sf[n][3] = 0.f;
            #pragma unroll
            for (int kcp = 0; kcp < 2; ++kcp) {
                unsigned d0, d1, d2, d3;
                // mats: (rows n*8+0..7) x k-chunks kcp*32 + {0,8,16,24}
                const unsigned addr = kbuf +
                    (unsigned)(((n*8 + (lane & 7)) * KSTRb + kcp*32 + (lane >> 3) * 8) * 2);
                ldsm_x4(d0, d1, d2, d3, addr);
                mma_bf16(sf[n], qa[2*kcp],     d0, d1);
                mma_bf16(sf[n], qa[2*kcp + 1], d2, d3);
            }
        }

        // ---- online softmax (rows grp / grp+8) ----
        float mx0 = fmaxf(fmaxf(sf[0][0], sf[0][1]), fmaxf(sf[1][0], sf[1][1]));
        mx0 = fmaxf(mx0, fmaxf(fmaxf(sf[2][0], sf[2][1]), fmaxf(sf[3][0], sf[3][1])));
        float mx1 = fmaxf(fmaxf(sf[0][2], sf[0][3]), fmaxf(sf[1][2], sf[1][3]));
        mx1 = fmaxf(mx1, fmaxf(fmaxf(sf[2][2], sf[2][3]), fmaxf(sf[3][2], sf[3][3])));
        mx0 = fmaxf(mx0, __shfl_xor_sync(0xffffffffu, mx0, 1));
        mx0 = fmaxf(mx0, __shfl_xor_sync(0xffffffffu, mx0, 2));
        mx1 = fmaxf(mx1, __shfl_xor_sync(0xffffffffu, mx1, 1));
        mx1 = fmaxf(mx1, __shfl_xor_sync(0xffffffffu, mx1, 2));

        const float mn0 = fmaxf(m0, mx0);
        const float mn1 = fmaxf(m1, mx1);
        const float al0 = __expf(m0 - mn0);
        const float al1 = __expf(m1 - mn1);

        float s0 = 0.f, s1 = 0.f;
        #pragma unroll
        for (int n = 0; n < 4; ++n) {
            sf[n][0] = __expf(sf[n][0] - mn0); s0 += sf[n][0];
            sf[n][1] = __expf(sf[n][1] - mn0); s0 += sf[n][1];
            sf[n][2] = __expf(sf[n][2] - mn1); s1 += sf[n][2];
            sf[n][3] = __expf(sf[n][3] - mn1); s1 += sf[n][3];
        }
        s0 += __shfl_xor_sync(0xffffffffu, s0, 1);
        s0 += __shfl_xor_sync(0xffffffffu, s0, 2);
        s1 += __shfl_xor_sync(0xffffffffu, s1, 1);
        s1 += __shfl_xor_sync(0xffffffffu, s1, 2);

        l0 = l0 * al0 + s0;  m0 = mn0;
        l1 = l1 * al1 + s1;  m1 = mn1;

        #pragma unroll
        for (int n = 0; n < 8; ++n) {
            of[n][0] *= al0; of[n][1] *= al0;
            of[n][2] *= al1; of[n][3] *= al1;
        }

        // ---- store P as bf16 pairs to per-warp-private smem rows ----
        {
            __nv_bfloat16* pr = &Ps[(w*16 + grp) * PSTRb];
            #pragma unroll
            for (int n = 0; n < 4; ++n) {
                *(unsigned*)&pr[n*8 + 2*tig]               = pack_bf16(sf[n][0], sf[n][1]);
                *(unsigned*)&pr[8*PSTRb + n*8 + 2*tig]     = pack_bf16(sf[n][2], sf[n][3]);
            }
        }
        __syncwarp();

        // ---- P A-fragments (pairs contiguous -> 32-bit LDS) ----
        unsigned pa[2][4];
        {
            const __nv_bfloat16* pr = &Ps[(w*16 + grp) * PSTRb];
            #pragma unroll
            for (int kc = 0; kc < 2; ++kc) {
                pa[kc][0] = *(const unsigned*)&pr[kc*16 + 2*tig];
                pa[kc][1] = *(const unsigned*)&pr[8*PSTRb + kc*16 + 2*tig];
                pa[kc][2] = *(const unsigned*)&pr[kc*16 + 8 + 2*tig];
                pa[kc][3] = *(const unsigned*)&pr[8*PSTRb + kc*16 + 8 + 2*tig];
            }
        }

        // ---- PV: O(16x64) += P(16x32) V(32x64) via ldmatrix.x4.trans ----
        #pragma unroll
        for (int kc = 0; kc < 2; ++kc) {
            #pragma unroll
            for (int np = 0; np < 4; ++np) {
                unsigned d0, d1, d2, d3;
                const unsigned addr = vbuf + (unsigned)(
                    ((kc*16 + ((lane >> 3) & 1) * 8 + (lane & 7)) * KSTRb
                     + np*16 + (lane >> 4) * 8) * 2);
                ldsm_x4_t(d0, d1, d2, d3, addr);
                mma_bf16(of[2*np],     pa[kc], d0, d1);
                mma_bf16(of[2*np + 1], pa[kc], d2, d3);
            }
        }
        __syncthreads();   // all reads of buf done before next-iter cp.async
    }

    // ---- epilogue: O / l (fp32 out) ----
    const float inv0 = 1.f / l0;
    const float inv1 = 1.f / l1;
    float* ob = O + (size_t)(q0 + w*16 + grp) * DM + h * DH;
    #pragma unroll
    for (int n = 0; n < 8; ++n) {
        *(float2*)&ob[n*8 + 2*tig] =
            make_float2(of[n][0] * inv0, of[n][1] * inv0);
        *(float2*)&ob[(size_t)8 * DM + n*8 + 2*tig] =
            make_float2(of[n][2] * inv1, of[n][3] * inv1);
    }
}

// ---------------------------------------------------------------------------
// out[row] = LayerNorm(A[row] + B[row]) * gamma + beta.  One block per row.
// ---------------------------------------------------------------------------
__global__ void __launch_bounds__(128)
add_ln_kernel(const float* __restrict__ A, const float* __restrict__ B,
              const float* __restrict__ gamma, const float* __restrict__ beta,
              float* __restrict__ O)
{
    __shared__ float red[4];
    const int row = blockIdx.x;
    const int t   = threadIdx.x;
    const int wid = t >> 5;
    const int lane = t & 31;

    const size_t base = (size_t)row * DM + t * 4;
    float4 a = *(const float4*)(A + base);
    float4 b = *(const float4*)(B + base);
    float4 v = make_float4(a.x + b.x, a.y + b.y, a.z + b.z, a.w + b.w);

    float s = v.x + v.y + v.z + v.w;
    #pragma unroll
    for (int o = 16; o > 0; o >>= 1) s += __shfl_xor_sync(0xffffffffu, s, o);
    if (lane == 0) red[wid] = s;
    __syncthreads();
    const float mu = (red[0] + red[1] + red[2] + red[3]) * (1.f / DM);

    float4 d = make_float4(v.x - mu, v.y - mu, v.z - mu, v.w - mu);
    float ss = d.x*d.x + d.y*d.y + d.z*d.z + d.w*d.w;
    #pragma unroll
    for (int o = 16; o > 0; o >>= 1) ss += __shfl_xor_sync(0xffffffffu, ss, o);
    __syncthreads();
    if (lane == 0) red[wid] = ss;
    __syncthreads();
    const float var  = (red[0] + red[1] + red[2] + red[3]) * (1.f / DM);
    const float rstd = rsqrtf(var + 1e-6f);

    float4 g  = *(const float4*)(gamma + t * 4);
    float4 be = *(const float4*)(beta  + t * 4);
    float4 o;
    o.x = d.x * rstd * g.x + be.x;
    o.y = d.y * rstd * g.y + be.y;
    o.z = d.z * rstd * g.z + be.z;
    o.w = d.w * rstd * g.w + be.w;
    *(float4*)(O + base) = o;
}

// ---------------------------------------------------------------------------
// kernel_launch
// ---------------------------------------------------------------------------
extern "C" void kernel_launch(void* const* d_in, const int* in_sizes, int n_in,
                              void* d_out, int out_size)
{
    const float* x       = (const float*)d_in[0];
    const float* wq_w    = (const float*)d_in[1];
    const float* wq_b    = (const float*)d_in[2];
    const float* wk_w    = (const float*)d_in[3];
    const float* wk_b    = (const float*)d_in[4];
    const float* wv_w    = (const float*)d_in[5];
    const float* wv_b    = (const float*)d_in[6];
    const float* dense_w = (const float*)d_in[7];
    const float* dense_b = (const float*)d_in[8];
    const float* l1_w    = (const float*)d_in[9];
    const float* l1_b    = (const float*)d_in[10];
    const float* l2_w    = (const float*)d_in[11];
    const float* l2_b    = (const float*)d_in[12];
    const float* ln1_g   = (const float*)d_in[13];
    const float* ln1_b   = (const float*)d_in[14];
    const float* ln2_g   = (const float*)d_in[15];
    const float* ln2_b   = (const float*)d_in[16];
    float* out = (float*)d_out;

    __nv_bfloat16 *Qb, *Kb, *Vb;
    float *CTX, *ATT, *O1, *Hh, *F;
    cudaGetSymbolAddress((void**)&Qb,  g_Qb);
    cudaGetSymbolAddress((void**)&Kb,  g_Kb);
    cudaGetSymbolAddress((void**)&Vb,  g_Vb);
    cudaGetSymbolAddress((void**)&CTX, g_CTX);
    cudaGetSymbolAddress((void**)&ATT, g_ATT);
    cudaGetSymbolAddress((void**)&O1,  g_O1);
    cudaGetSymbolAddress((void**)&Hh,  g_H);
    cudaGetSymbolAddress((void**)&F,   g_F);

    // QKV projections, batched (bf16 outputs; Q pre-scaled by 1/sqrt(DH))
    gemm_tc_kernel<false, true><<<dim3(DM/128, S_LEN/128, 3), 256>>>(
        x,
        wq_w, wq_b, Qb,
        wk_w, wk_b, Kb,
        wv_w, wv_b, Vb,
        DM, DM, 0.125f, 1.f, 1.f);

    // attention (bf16 tensor cores)
    flash_attn_bf16_kernel<<<dim3(S_LEN / 64, NH), 128>>>(Qb, Kb, Vb, CTX);

    // dense proj + add&norm
    gemm_tc_kernel<false, false><<<dim3(DM/128, S_LEN/128, 1), 256>>>(
        CTX,
        dense_w, dense_b, ATT,
        dense_w, dense_b, ATT,
        dense_w, dense_b, ATT,
        DM, DM, 1.f, 1.f, 1.f);
    add_ln_kernel<<<S_LEN, 128>>>(x, ATT, ln1_g, ln1_b, O1);

    // FFN + add&norm
    gemm_tc_kernel<true, false><<<dim3(DFF_/128, S_LEN/128, 1), 256>>>(
        O1,
        l1_w, l1_b, Hh,
        l1_w, l1_b, Hh,
        l1_w, l1_b, Hh,
        DFF_, DM, 1.f, 1.f, 1.f);
    gemm_tc_kernel<false, false><<<dim3(DM/128, S_LEN/128, 1), 256>>>(
        Hh,
        l2_w, l2_b, F,
        l2_w, l2_b, F,
        l2_w, l2_b, F,
        DM, DFF_, 1.f, 1.f, 1.f);
    add_ln_kernel<<<S_LEN, 128>>>(O1, F, ln2_g, ln2_b, out);
}